// round 4
// baseline (speedup 1.0000x reference)
#include <cuda_runtime.h>
#include <cuda_bf16.h>
#include <cstdint>
#include <math.h>

// ===================== problem constants =====================
constexpr int Bsz = 2;
constexpr int Hn  = 16;
constexpr int Sn  = 2048;
constexpr int Dh  = 128;

constexpr int BQ = 128;   // q rows per CTA (8 warps x 16 rows)
constexpr int BK = 64;    // k cols per iteration
constexpr int NT = 256;   // 8 warps

constexpr int RSB = 272;  // smem row stride in bytes (136 bf16) -> conflict-free ldmatrix

// smem byte offsets
constexpr int SM_QHI = 0;
constexpr int SM_QLO = SM_QHI + BQ * RSB;          // 34816
constexpr int SM_KHI = SM_QLO + BQ * RSB;          // 69632
constexpr int SM_KLO = SM_KHI + BK * RSB;          // 87040
constexpr int SM_V0  = SM_KLO + BK * RSB;          // 104448
constexpr int VBUF   = 2 * BK * RSB;               // 34816 (hi+lo per buffer)
constexpr int DVL    = BK * RSB;                   // 17408 (lo offset within buffer)
constexpr int SM_AM  = SM_V0 + 2 * VBUF;           // 174080
constexpr int SM_TOTAL = SM_AM + BK * 4;           // 174336 B

// ===================== helpers =====================
static __device__ __forceinline__ uint32_t smem_u32(const void* p) {
    uint32_t a;
    asm("{ .reg .u64 t; cvta.to.shared.u64 t, %1; cvt.u32.u64 %0, t; }" : "=r"(a) : "l"(p));
    return a;
}
static __device__ __forceinline__ void ldsm4(uint32_t* r, uint32_t a) {
    asm volatile("ldmatrix.sync.aligned.m8n8.x4.shared.b16 {%0,%1,%2,%3}, [%4];"
                 : "=r"(r[0]), "=r"(r[1]), "=r"(r[2]), "=r"(r[3]) : "r"(a));
}
static __device__ __forceinline__ void ldsm4t(uint32_t* r, uint32_t a) {
    asm volatile("ldmatrix.sync.aligned.m8n8.x4.trans.shared.b16 {%0,%1,%2,%3}, [%4];"
                 : "=r"(r[0]), "=r"(r[1]), "=r"(r[2]), "=r"(r[3]) : "r"(a));
}
static __device__ __forceinline__ void mma_bf16(float* c, const uint32_t* a, const uint32_t* b) {
    asm volatile("mma.sync.aligned.m16n8k16.row.col.f32.bf16.bf16.f32 "
                 "{%0,%1,%2,%3},{%4,%5,%6,%7},{%8,%9},{%0,%1,%2,%3};"
                 : "+f"(c[0]), "+f"(c[1]), "+f"(c[2]), "+f"(c[3])
                 : "r"(a[0]), "r"(a[1]), "r"(a[2]), "r"(a[3]), "r"(b[0]), "r"(b[1]));
}
// pack two f32 -> bf16x2 (first arg in low half)
static __device__ __forceinline__ uint32_t cvt2(float lo, float hi) {
    uint32_t r;
    asm("cvt.rn.bf16x2.f32 %0, %1, %2;" : "=r"(r) : "f"(hi), "f"(lo));
    return r;
}
static __device__ __forceinline__ float bflo(uint32_t u) { return __uint_as_float(u << 16); }
static __device__ __forceinline__ float bfhi(uint32_t u) { return __uint_as_float(u & 0xffff0000u); }

// software exp on FMA pipe (x <= 0 expected; -inf / -1e30 -> ~0)
static __device__ __forceinline__ float fexp(float x) {
    x = fmaxf(x, -87.3f);
    const float L2E = 1.4426950408889634f;
    float r = fmaf(x, L2E, 12582912.0f);          // round to int via magic
    float n = r - 12582912.0f;
    float t = fmaf(x, L2E, -n);                   // frac in [-0.5, 0.5]
    float p =              1.5403530393e-4f;
    p = fmaf(p, t, 1.3333558146e-3f);
    p = fmaf(p, t, 9.6181291076e-3f);
    p = fmaf(p, t, 5.5504108665e-2f);
    p = fmaf(p, t, 2.4022650696e-1f);
    p = fmaf(p, t, 6.9314718056e-1f);
    p = fmaf(p, t, 1.0f);
    int sc = (__float_as_int(r) - 0x4B400000) << 23;
    return __uint_as_float(__float_as_int(p) + sc);
}

// load+split a 64x128 fp32 tile into bf16 hi/lo smem arrays (16B STS chunks)
static __device__ __forceinline__ void load_tile64(const float* __restrict__ g,
                                                   char* hib, char* lob, int tid) {
    #pragma unroll
    for (int it = 0; it < 4; ++it) {
        int e = it * NT + tid;                 // 1024 chunks of 8 floats
        int row = e >> 4, c8 = e & 15;
        const float4* src = reinterpret_cast<const float4*>(g) + 2 * e;
        float4 x = src[0], y = src[1];
        uint32_t hx01 = cvt2(x.x, x.y), hx23 = cvt2(x.z, x.w);
        uint32_t hy01 = cvt2(y.x, y.y), hy23 = cvt2(y.z, y.w);
        uint32_t lx01 = cvt2(x.x - bflo(hx01), x.y - bfhi(hx01));
        uint32_t lx23 = cvt2(x.z - bflo(hx23), x.w - bfhi(hx23));
        uint32_t ly01 = cvt2(y.x - bflo(hy01), y.y - bfhi(hy01));
        uint32_t ly23 = cvt2(y.z - bflo(hy23), y.w - bfhi(hy23));
        int off = row * RSB + c8 * 16;
        *reinterpret_cast<uint4*>(hib + off) = make_uint4(hx01, hx23, hy01, hy23);
        *reinterpret_cast<uint4*>(lob + off) = make_uint4(lx01, lx23, ly01, ly23);
    }
}

// one PV chunk: 16 k-rows (t) x 128 d-cols, 3-pass hi/lo split
static __device__ __forceinline__ void pv_chunk(float* o, const uint32_t* ph, const uint32_t* pl,
                                                uint32_t voff, int t) {
    #pragma unroll
    for (int g = 0; g < 8; ++g) {
        uint32_t vh4[4], vl4[4];
        ldsm4t(vh4, voff + t * (16 * RSB) + g * 32);
        ldsm4t(vl4, voff + DVL + t * (16 * RSB) + g * 32);
        mma_bf16(o + 8 * g,     ph, vh4);
        mma_bf16(o + 8 * g,     ph, vl4);
        mma_bf16(o + 8 * g,     pl, vh4);
        mma_bf16(o + 8 * g + 4, ph, vh4 + 2);
        mma_bf16(o + 8 * g + 4, ph, vl4 + 2);
        mma_bf16(o + 8 * g + 4, pl, vh4 + 2);
    }
}

// ===================== kernel =====================
__global__ __launch_bounds__(NT, 1)
void fa_mma_kernel(const float* __restrict__ q, const float* __restrict__ k,
                   const float* __restrict__ v, const float* __restrict__ am,
                   const float* __restrict__ hm, float* __restrict__ out)
{
    extern __shared__ char smem[];
    const uint32_t sbase = smem_u32(smem);
    float* am_s = reinterpret_cast<float*>(smem + SM_AM);

    const int tid = threadIdx.x, wid = tid >> 5, lane = tid & 31;
    const int bh = blockIdx.y, b = bh >> 4, h = bh & 15;
    const int qt = (int)gridDim.x - 1 - (int)blockIdx.x;   // heavy tiles first
    const int q0 = qt * BQ;
    const int nkt = 2 * (qt + 1);

    const float* qg  = q + ((size_t)bh * Sn + q0) * Dh;
    const float* kg  = k + (size_t)bh * Sn * Dh;
    const float* vg  = v + (size_t)bh * Sn * Dh;
    const float* amg = am + (size_t)b * Sn;
    const float  hmv = hm[h];

    // ---- load Q tile, split fp32 -> bf16 hi/lo ----
    #pragma unroll
    for (int it = 0; it < 8; ++it) {
        int e = it * NT + tid;                 // 2048 chunks of 8 floats
        int row = e >> 4, c8 = e & 15;
        const float4* src = reinterpret_cast<const float4*>(qg) + 2 * e;
        float4 x = src[0], y = src[1];
        uint32_t hx01 = cvt2(x.x, x.y), hx23 = cvt2(x.z, x.w);
        uint32_t hy01 = cvt2(y.x, y.y), hy23 = cvt2(y.z, y.w);
        uint32_t lx01 = cvt2(x.x - bflo(hx01), x.y - bfhi(hx01));
        uint32_t lx23 = cvt2(x.z - bflo(hx23), x.w - bfhi(hx23));
        uint32_t ly01 = cvt2(y.x - bflo(hy01), y.y - bfhi(hy01));
        uint32_t ly23 = cvt2(y.z - bflo(hy23), y.w - bfhi(hy23));
        int off = row * RSB + c8 * 16;
        *reinterpret_cast<uint4*>(smem + SM_QHI + off) = make_uint4(hx01, hx23, hy01, hy23);
        *reinterpret_cast<uint4*>(smem + SM_QLO + off) = make_uint4(lx01, lx23, ly01, ly23);
    }

    // per-lane ldmatrix base addresses
    const int m0 = wid * 16;
    const uint32_t qoff = sbase + SM_QHI + (m0 + (lane & 15)) * RSB + ((lane >> 4) & 1) * 16;
    const uint32_t koff = sbase + SM_KHI + ((lane & 7) + ((lane >> 4) & 1) * 8) * RSB + ((lane >> 3) & 1) * 16;
    const uint32_t vlaneoff = ((lane & 7) + ((lane >> 3) & 1) * 8) * RSB + ((lane >> 4) & 1) * 16;
    constexpr int DQL = SM_QLO - SM_QHI;
    constexpr int DKL = SM_KLO - SM_KHI;

    float o[64];
    #pragma unroll
    for (int i = 0; i < 64; ++i) o[i] = 0.0f;
    float M0 = -INFINITY, M1 = -INFINITY, L0 = 0.0f, L1 = 0.0f;
    uint32_t ph[4][4], pl[4][4];   // P fragments of previous tile

    const int rg0 = q0 + m0 + (lane >> 2);   // global q row (upper)
    const int rg1 = rg0 + 8;
    const int c00 = 2 * (lane & 3);          // local col base within n8 tile

    for (int kt = 0; kt < nkt; ++kt) {
        __syncthreads();
        load_tile64(kg + (size_t)kt * BK * Dh, smem + SM_KHI, smem + SM_KLO, tid);
        load_tile64(vg + (size_t)kt * BK * Dh,
                    smem + SM_V0 + (kt & 1) * VBUF,
                    smem + SM_V0 + (kt & 1) * VBUF + DVL, tid);
        if (tid < BK) am_s[tid] = amg[kt * BK + tid];
        __syncthreads();

        // ---- S = Q K^T (3-pass split, 16x64 per warp) ----
        float sv[32];
        #pragma unroll
        for (int i = 0; i < 32; ++i) sv[i] = 0.0f;
        #pragma unroll
        for (int t = 0; t < 8; ++t) {                 // k16 tiles over d=128
            uint32_t ah[4], al[4];
            ldsm4(ah, qoff + t * 32);
            ldsm4(al, qoff + DQL + t * 32);
            #pragma unroll
            for (int g = 0; g < 4; ++g) {             // n16 groups over 64 cols
                uint32_t bh4[4], bl4[4];
                ldsm4(bh4, koff + g * (16 * RSB) + t * 32);
                ldsm4(bl4, koff + DKL + g * (16 * RSB) + t * 32);
                mma_bf16(sv + 8 * g,     ah, bh4);
                mma_bf16(sv + 8 * g,     ah, bl4);
                mma_bf16(sv + 8 * g,     al, bh4);
                mma_bf16(sv + 8 * g + 4, ah, bh4 + 2);
                mma_bf16(sv + 8 * g + 4, ah, bl4 + 2);
                mma_bf16(sv + 8 * g + 4, al, bh4 + 2);
            }
        }

        // ---- causal mask + additive attn_mask ----
        float amr[16];
        #pragma unroll
        for (int n = 0; n < 8; ++n) {
            float2 a2 = *reinterpret_cast<const float2*>(&am_s[8 * n + c00]);
            amr[2 * n] = a2.x; amr[2 * n + 1] = a2.y;
        }
        if (kt >= nkt - 2) {   // only diagonal-touching tiles need element checks
            #pragma unroll
            for (int n = 0; n < 8; ++n) {
                int cg = kt * BK + 8 * n + c00;
                sv[4*n+0] = (cg     <= rg0) ? sv[4*n+0] + amr[2*n]   : -1e30f;
                sv[4*n+1] = (cg + 1 <= rg0) ? sv[4*n+1] + amr[2*n+1] : -1e30f;
                sv[4*n+2] = (cg     <= rg1) ? sv[4*n+2] + amr[2*n]   : -1e30f;
                sv[4*n+3] = (cg + 1 <= rg1) ? sv[4*n+3] + amr[2*n+1] : -1e30f;
            }
        } else {
            #pragma unroll
            for (int n = 0; n < 8; ++n) {
                sv[4*n+0] += amr[2*n];   sv[4*n+1] += amr[2*n+1];
                sv[4*n+2] += amr[2*n];   sv[4*n+3] += amr[2*n+1];
            }
        }

        // ---- row max + rescale factors ----
        float t0 = -INFINITY, t1 = -INFINITY;
        #pragma unroll
        for (int n = 0; n < 8; ++n) {
            t0 = fmaxf(t0, fmaxf(sv[4*n+0], sv[4*n+1]));
            t1 = fmaxf(t1, fmaxf(sv[4*n+2], sv[4*n+3]));
        }
        t0 = fmaxf(t0, __shfl_xor_sync(0xffffffffu, t0, 1));
        t0 = fmaxf(t0, __shfl_xor_sync(0xffffffffu, t0, 2));
        t1 = fmaxf(t1, __shfl_xor_sync(0xffffffffu, t1, 1));
        t1 = fmaxf(t1, __shfl_xor_sync(0xffffffffu, t1, 2));
        float M0n = fmaxf(M0, t0), M1n = fmaxf(M1, t1);
        float a0 = fexp(M0 - M0n), a1 = fexp(M1 - M1n);
        M0 = M0n; M1 = M1n;

        // ---- merged region: PV(kt-1) HMMAs interleaved with exp/convert(kt) ----
        float l0 = 0.0f, l1 = 0.0f;
        uint32_t phN[4][4], plN[4][4];

        #define EXP_CHUNK(t)                                                        \
            _Pragma("unroll")                                                       \
            for (int r = 0; r < 8; r += 4) {                                        \
                float p0 = fexp(sv[8*(t)+r+0] - M0n);                               \
                float p1 = fexp(sv[8*(t)+r+1] - M0n);                               \
                float p2 = fexp(sv[8*(t)+r+2] - M1n);                               \
                float p3 = fexp(sv[8*(t)+r+3] - M1n);                               \
                l0 += p0 + p1; l1 += p2 + p3;                                       \
                int rix = r >> 1;                                                   \
                uint32_t hh0 = cvt2(p0, p1);                                        \
                phN[t][rix]   = hh0;                                                \
                plN[t][rix]   = cvt2(p0 - bflo(hh0), p1 - bfhi(hh0));               \
                uint32_t hh1 = cvt2(p2, p3);                                        \
                phN[t][rix+1] = hh1;                                                \
                plN[t][rix+1] = cvt2(p2 - bflo(hh1), p3 - bfhi(hh1));               \
            }

        if (kt > 0) {
            const uint32_t vprev = sbase + SM_V0 + ((kt - 1) & 1) * VBUF + vlaneoff;
            #pragma unroll
            for (int t = 0; t < 4; ++t) {
                pv_chunk(o, ph[t], pl[t], vprev, t);
                EXP_CHUNK(t)
            }
        } else {
            #pragma unroll
            for (int t = 0; t < 4; ++t) { EXP_CHUNK(t) }
        }
        #undef EXP_CHUNK

        // ---- L update + O rescale (ordered after PV) ----
        l0 += __shfl_xor_sync(0xffffffffu, l0, 1);
        l0 += __shfl_xor_sync(0xffffffffu, l0, 2);
        l1 += __shfl_xor_sync(0xffffffffu, l1, 1);
        l1 += __shfl_xor_sync(0xffffffffu, l1, 2);
        L0 = L0 * a0 + l0;
        L1 = L1 * a1 + l1;
        #pragma unroll
        for (int n = 0; n < 16; ++n) {
            o[4*n+0] *= a0; o[4*n+1] *= a0;
            o[4*n+2] *= a1; o[4*n+3] *= a1;
        }
        #pragma unroll
        for (int t = 0; t < 4; ++t)
            #pragma unroll
            for (int j = 0; j < 4; ++j) { ph[t][j] = phN[t][j]; pl[t][j] = plN[t][j]; }
    }

    // ---- flush last tile's PV ----
    {
        const uint32_t vlast = sbase + SM_V0 + ((nkt - 1) & 1) * VBUF + vlaneoff;
        #pragma unroll
        for (int t = 0; t < 4; ++t)
            pv_chunk(o, ph[t], pl[t], vlast, t);
    }

    // ---- epilogue: normalize, head_mask, store ----
    float li0 = hmv / L0, li1 = hmv / L1;
    float* o0 = out + ((size_t)bh * Sn + rg0) * Dh;
    float* o1 = o0 + 8 * Dh;
    #pragma unroll
    for (int n = 0; n < 16; ++n) {
        int c = 8 * n + c00;
        *reinterpret_cast<float2*>(o0 + c) = make_float2(o[4*n+0] * li0, o[4*n+1] * li0);
        *reinterpret_cast<float2*>(o1 + c) = make_float2(o[4*n+2] * li1, o[4*n+3] * li1);
    }
}

// ===================== launch =====================
extern "C" void kernel_launch(void* const* d_in, const int* in_sizes, int n_in,
                              void* d_out, int out_size)
{
    const float* q  = (const float*)d_in[0];
    const float* k  = (const float*)d_in[1];
    const float* v  = (const float*)d_in[2];
    const float* am = (const float*)d_in[3];
    const float* hm = (const float*)d_in[4];
    float* out = (float*)d_out;

    cudaFuncSetAttribute(fa_mma_kernel,
                         cudaFuncAttributeMaxDynamicSharedMemorySize, SM_TOTAL);

    dim3 grid(Sn / BQ, Bsz * Hn);   // (16 q-tiles, 32 bh)
    fa_mma_kernel<<<grid, NT, SM_TOTAL>>>(q, k, v, am, hm, out);
}

// round 5
// speedup vs baseline: 1.0519x; 1.0519x over previous
#include <cuda_runtime.h>
#include <cuda_bf16.h>
#include <cstdint>
#include <math.h>

// ===================== problem constants =====================
constexpr int Bsz = 2;
constexpr int Hn  = 16;
constexpr int Sn  = 2048;
constexpr int Dh  = 128;

constexpr int BQ = 64;    // q rows per CTA (4 warps x 16 rows)
constexpr int BK = 64;    // k cols per iteration
constexpr int NT = 128;   // 4 warps

constexpr int RSB = 272;  // smem row stride in bytes (136 bf16) -> conflict-free ldmatrix

// smem byte offsets (per-tile hi/lo pairs, each 64 rows x 272B)
constexpr int SM_QHI = 0;
constexpr int SM_QLO = SM_QHI + BQ * RSB;          // 17408
constexpr int SM_KHI = SM_QLO + BQ * RSB;          // 34816
constexpr int SM_KLO = SM_KHI + BK * RSB;          // 52224
constexpr int SM_VHI = SM_KLO + BK * RSB;          // 69632
constexpr int SM_VLO = SM_VHI + BK * RSB;          // 87040
constexpr int SM_AM  = SM_VLO + BK * RSB;          // 104448
constexpr int SM_TOTAL = SM_AM + BK * 4;           // 104704 B  (x2 CTAs = 209.4KB/SM)

// ===================== helpers =====================
static __device__ __forceinline__ uint32_t smem_u32(const void* p) {
    uint32_t a;
    asm("{ .reg .u64 t; cvta.to.shared.u64 t, %1; cvt.u32.u64 %0, t; }" : "=r"(a) : "l"(p));
    return a;
}
static __device__ __forceinline__ void ldsm4(uint32_t* r, uint32_t a) {
    asm volatile("ldmatrix.sync.aligned.m8n8.x4.shared.b16 {%0,%1,%2,%3}, [%4];"
                 : "=r"(r[0]), "=r"(r[1]), "=r"(r[2]), "=r"(r[3]) : "r"(a));
}
static __device__ __forceinline__ void ldsm4t(uint32_t* r, uint32_t a) {
    asm volatile("ldmatrix.sync.aligned.m8n8.x4.trans.shared.b16 {%0,%1,%2,%3}, [%4];"
                 : "=r"(r[0]), "=r"(r[1]), "=r"(r[2]), "=r"(r[3]) : "r"(a));
}
static __device__ __forceinline__ void mma_bf16(float* c, const uint32_t* a, const uint32_t* b) {
    asm volatile("mma.sync.aligned.m16n8k16.row.col.f32.bf16.bf16.f32 "
                 "{%0,%1,%2,%3},{%4,%5,%6,%7},{%8,%9},{%0,%1,%2,%3};"
                 : "+f"(c[0]), "+f"(c[1]), "+f"(c[2]), "+f"(c[3])
                 : "r"(a[0]), "r"(a[1]), "r"(a[2]), "r"(a[3]), "r"(b[0]), "r"(b[1]));
}
// pack two f32 -> bf16x2 (first arg in low half)
static __device__ __forceinline__ uint32_t cvt2(float lo, float hi) {
    uint32_t r;
    asm("cvt.rn.bf16x2.f32 %0, %1, %2;" : "=r"(r) : "f"(hi), "f"(lo));
    return r;
}
static __device__ __forceinline__ float bflo(uint32_t u) { return __uint_as_float(u << 16); }
static __device__ __forceinline__ float bfhi(uint32_t u) { return __uint_as_float(u & 0xffff0000u); }

// software exp on FMA pipe (x <= 0 expected; -inf / -1e30 -> ~0)
static __device__ __forceinline__ float fexp(float x) {
    x = fmaxf(x, -87.3f);
    const float L2E = 1.4426950408889634f;
    float r = fmaf(x, L2E, 12582912.0f);          // round to int via magic
    float n = r - 12582912.0f;
    float t = fmaf(x, L2E, -n);                   // frac in [-0.5, 0.5]
    float p =              1.5403530393e-4f;
    p = fmaf(p, t, 1.3333558146e-3f);
    p = fmaf(p, t, 9.6181291076e-3f);
    p = fmaf(p, t, 5.5504108665e-2f);
    p = fmaf(p, t, 2.4022650696e-1f);
    p = fmaf(p, t, 6.9314718056e-1f);
    p = fmaf(p, t, 1.0f);
    int sc = (__float_as_int(r) - 0x4B400000) << 23;
    return __uint_as_float(__float_as_int(p) + sc);
}

// load+split a 64x128 fp32 tile into bf16 hi/lo smem arrays (16B STS chunks)
static __device__ __forceinline__ void load_tile64(const float* __restrict__ g,
                                                   char* hib, char* lob, int tid) {
    #pragma unroll
    for (int it = 0; it < 8; ++it) {
        int e = it * NT + tid;                 // 1024 chunks of 8 floats
        int row = e >> 4, c8 = e & 15;
        const float4* src = reinterpret_cast<const float4*>(g) + 2 * e;
        float4 x = src[0], y = src[1];
        uint32_t hx01 = cvt2(x.x, x.y), hx23 = cvt2(x.z, x.w);
        uint32_t hy01 = cvt2(y.x, y.y), hy23 = cvt2(y.z, y.w);
        uint32_t lx01 = cvt2(x.x - bflo(hx01), x.y - bfhi(hx01));
        uint32_t lx23 = cvt2(x.z - bflo(hx23), x.w - bfhi(hx23));
        uint32_t ly01 = cvt2(y.x - bflo(hy01), y.y - bfhi(hy01));
        uint32_t ly23 = cvt2(y.z - bflo(hy23), y.w - bfhi(hy23));
        int off = row * RSB + c8 * 16;
        *reinterpret_cast<uint4*>(hib + off) = make_uint4(hx01, hx23, hy01, hy23);
        *reinterpret_cast<uint4*>(lob + off) = make_uint4(lx01, lx23, ly01, ly23);
    }
}

// ===================== kernel =====================
__global__ __launch_bounds__(NT, 2)
void fa_mma_kernel(const float* __restrict__ q, const float* __restrict__ k,
                   const float* __restrict__ v, const float* __restrict__ am,
                   const float* __restrict__ hm, float* __restrict__ out)
{
    extern __shared__ char smem[];
    const uint32_t sbase = smem_u32(smem);
    float* am_s = reinterpret_cast<float*>(smem + SM_AM);

    const int tid = threadIdx.x, wid = tid >> 5, lane = tid & 31;
    const int bh = blockIdx.y, b = bh >> 4, h = bh & 15;
    const int qt = (int)gridDim.x - 1 - (int)blockIdx.x;   // heavy tiles first
    const int q0 = qt * BQ;
    const int nkt = qt + 1;                                // BQ == BK

    const float* qg  = q + ((size_t)bh * Sn + q0) * Dh;
    const float* kg  = k + (size_t)bh * Sn * Dh;
    const float* vg  = v + (size_t)bh * Sn * Dh;
    const float* amg = am + (size_t)b * Sn;
    const float  hmv = hm[h];

    // ---- load Q tile, split fp32 -> bf16 hi/lo ----
    load_tile64(qg, smem + SM_QHI, smem + SM_QLO, tid);

    // per-lane ldmatrix base addresses
    const int m0 = wid * 16;
    const uint32_t qoff = sbase + SM_QHI + (m0 + (lane & 15)) * RSB + ((lane >> 4) & 1) * 16;
    const uint32_t koff = sbase + SM_KHI + ((lane & 7) + ((lane >> 4) & 1) * 8) * RSB + ((lane >> 3) & 1) * 16;
    const uint32_t voff = sbase + SM_VHI + ((lane & 7) + ((lane >> 3) & 1) * 8) * RSB + ((lane >> 4) & 1) * 16;
    constexpr int DQL = SM_QLO - SM_QHI;
    constexpr int DKL = SM_KLO - SM_KHI;
    constexpr int DVL = SM_VLO - SM_VHI;

    float o[64];
    #pragma unroll
    for (int i = 0; i < 64; ++i) o[i] = 0.0f;
    float M0 = -INFINITY, M1 = -INFINITY, L0 = 0.0f, L1 = 0.0f;

    const int rg0 = q0 + m0 + (lane >> 2);   // global q row (upper)
    const int rg1 = rg0 + 8;
    const int c00 = 2 * (lane & 3);          // local col base within n8 tile

    for (int kt = 0; kt < nkt; ++kt) {
        __syncthreads();
        load_tile64(kg + (size_t)kt * BK * Dh, smem + SM_KHI, smem + SM_KLO, tid);
        load_tile64(vg + (size_t)kt * BK * Dh, smem + SM_VHI, smem + SM_VLO, tid);
        if (tid < BK) am_s[tid] = amg[kt * BK + tid];
        __syncthreads();

        // ---- S = Q K^T (3-pass split, 16x64 per warp) ----
        float sv[32];
        #pragma unroll
        for (int i = 0; i < 32; ++i) sv[i] = 0.0f;
        #pragma unroll
        for (int t = 0; t < 8; ++t) {                 // k16 tiles over d=128
            uint32_t ah[4], al[4];
            ldsm4(ah, qoff + t * 32);
            ldsm4(al, qoff + DQL + t * 32);
            #pragma unroll
            for (int g = 0; g < 4; ++g) {             // n16 groups over 64 cols
                uint32_t bh4[4], bl4[4];
                ldsm4(bh4, koff + g * (16 * RSB) + t * 32);
                ldsm4(bl4, koff + DKL + g * (16 * RSB) + t * 32);
                mma_bf16(sv + 8 * g,     ah, bh4);
                mma_bf16(sv + 8 * g,     ah, bl4);
                mma_bf16(sv + 8 * g,     al, bh4);
                mma_bf16(sv + 8 * g + 4, ah, bh4 + 2);
                mma_bf16(sv + 8 * g + 4, ah, bl4 + 2);
                mma_bf16(sv + 8 * g + 4, al, bh4 + 2);
            }
        }

        // ---- causal mask + additive attn_mask ----
        float amr[16];
        #pragma unroll
        for (int n = 0; n < 8; ++n) {
            float2 a2 = *reinterpret_cast<const float2*>(&am_s[8 * n + c00]);
            amr[2 * n] = a2.x; amr[2 * n + 1] = a2.y;
        }
        if (kt == nkt - 1) {   // only the diagonal tile needs element checks
            #pragma unroll
            for (int n = 0; n < 8; ++n) {
                int cg = kt * BK + 8 * n + c00;
                sv[4*n+0] = (cg     <= rg0) ? sv[4*n+0] + amr[2*n]   : -1e30f;
                sv[4*n+1] = (cg + 1 <= rg0) ? sv[4*n+1] + amr[2*n+1] : -1e30f;
                sv[4*n+2] = (cg     <= rg1) ? sv[4*n+2] + amr[2*n]   : -1e30f;
                sv[4*n+3] = (cg + 1 <= rg1) ? sv[4*n+3] + amr[2*n+1] : -1e30f;
            }
        } else {
            #pragma unroll
            for (int n = 0; n < 8; ++n) {
                sv[4*n+0] += amr[2*n];   sv[4*n+1] += amr[2*n+1];
                sv[4*n+2] += amr[2*n];   sv[4*n+3] += amr[2*n+1];
            }
        }

        // ---- online softmax (intra-quad shuffles only) ----
        float t0 = -INFINITY, t1 = -INFINITY;
        #pragma unroll
        for (int n = 0; n < 8; ++n) {
            t0 = fmaxf(t0, fmaxf(sv[4*n+0], sv[4*n+1]));
            t1 = fmaxf(t1, fmaxf(sv[4*n+2], sv[4*n+3]));
        }
        t0 = fmaxf(t0, __shfl_xor_sync(0xffffffffu, t0, 1));
        t0 = fmaxf(t0, __shfl_xor_sync(0xffffffffu, t0, 2));
        t1 = fmaxf(t1, __shfl_xor_sync(0xffffffffu, t1, 1));
        t1 = fmaxf(t1, __shfl_xor_sync(0xffffffffu, t1, 2));
        float M0n = fmaxf(M0, t0), M1n = fmaxf(M1, t1);
        float a0 = fexp(M0 - M0n), a1 = fexp(M1 - M1n);
        M0 = M0n; M1 = M1n;

        float l0 = 0.0f, l1 = 0.0f;
        #pragma unroll
        for (int n = 0; n < 8; ++n) {
            sv[4*n+0] = fexp(sv[4*n+0] - M0n);
            sv[4*n+1] = fexp(sv[4*n+1] - M0n);
            l0 += sv[4*n+0] + sv[4*n+1];
            sv[4*n+2] = fexp(sv[4*n+2] - M1n);
            sv[4*n+3] = fexp(sv[4*n+3] - M1n);
            l1 += sv[4*n+2] + sv[4*n+3];
        }
        l0 += __shfl_xor_sync(0xffffffffu, l0, 1);
        l0 += __shfl_xor_sync(0xffffffffu, l0, 2);
        l1 += __shfl_xor_sync(0xffffffffu, l1, 1);
        l1 += __shfl_xor_sync(0xffffffffu, l1, 2);
        L0 = L0 * a0 + l0;
        L1 = L1 * a1 + l1;
        #pragma unroll
        for (int n = 0; n < 16; ++n) {
            o[4*n+0] *= a0; o[4*n+1] *= a0;
            o[4*n+2] *= a1; o[4*n+3] *= a1;
        }

        // ---- P -> bf16 hi/lo A-fragments ----
        uint32_t ph[4][4], pl[4][4];
        #pragma unroll
        for (int t = 0; t < 4; ++t) {
            #pragma unroll
            for (int rix = 0; rix < 4; ++rix) {
                float f0 = sv[8*t + 2*rix], f1 = sv[8*t + 2*rix + 1];
                uint32_t hh = cvt2(f0, f1);
                ph[t][rix] = hh;
                pl[t][rix] = cvt2(f0 - bflo(hh), f1 - bfhi(hh));
            }
        }

        // ---- O += P V (3-pass split, 16x128 per warp) ----
        #pragma unroll
        for (int t = 0; t < 4; ++t) {                 // k16 tiles over BK=64
            #pragma unroll
            for (int g = 0; g < 8; ++g) {             // n16 groups over d=128
                uint32_t vh4[4], vl4[4];
                ldsm4t(vh4, voff + t * (16 * RSB) + g * 32);
                ldsm4t(vl4, voff + DVL + t * (16 * RSB) + g * 32);
                mma_bf16(o + 8 * g,     ph[t], vh4);
                mma_bf16(o + 8 * g,     ph[t], vl4);
                mma_bf16(o + 8 * g,     pl[t], vh4);
                mma_bf16(o + 8 * g + 4, ph[t], vh4 + 2);
                mma_bf16(o + 8 * g + 4, ph[t], vl4 + 2);
                mma_bf16(o + 8 * g + 4, pl[t], vh4 + 2);
            }
        }
    }

    // ---- epilogue: normalize, head_mask, store ----
    float li0 = hmv / L0, li1 = hmv / L1;
    float* o0 = out + ((size_t)bh * Sn + rg0) * Dh;
    float* o1 = o0 + 8 * Dh;
    #pragma unroll
    for (int n = 0; n < 16; ++n) {
        int c = 8 * n + c00;
        *reinterpret_cast<float2*>(o0 + c) = make_float2(o[4*n+0] * li0, o[4*n+1] * li0);
        *reinterpret_cast<float2*>(o1 + c) = make_float2(o[4*n+2] * li1, o[4*n+3] * li1);
    }
}

// ===================== launch =====================
extern "C" void kernel_launch(void* const* d_in, const int* in_sizes, int n_in,
                              void* d_out, int out_size)
{
    const float* q  = (const float*)d_in[0];
    const float* k  = (const float*)d_in[1];
    const float* v  = (const float*)d_in[2];
    const float* am = (const float*)d_in[3];
    const float* hm = (const float*)d_in[4];
    float* out = (float*)d_out;

    cudaFuncSetAttribute(fa_mma_kernel,
                         cudaFuncAttributeMaxDynamicSharedMemorySize, SM_TOTAL);

    dim3 grid(Sn / BQ, Bsz * Hn);   // (32 q-tiles, 32 bh)
    fa_mma_kernel<<<grid, NT, SM_TOTAL>>>(q, k, v, am, hm, out);
}